// round 6
// baseline (speedup 1.0000x reference)
#include <cuda_runtime.h>
#include <math.h>

#define D       256
#define PD      258                     // padded dim (zero border)
#define NA      360
#define SR      8                       // strip rows owned per strip
#define NS      (D / SR)                // 32 strips
#define BROWS   (SR + 2)                // 10 buffer rows
#define STRIPF4 (BROWS * PD)            // 2580 float4
#define ROWB    (PD * 16)               // 4128 bytes per padded row
#define NTH     512
#define SMEMB   (2 * STRIPF4 * 16)      // 82560 bytes (double buffer)

// Padded, pixel-major, 4-batch-packed images with zero border.
// g_pad[0][g] : y-major  (padded row = y+1, col = x+1)
// g_pad[1][g] : x-major  (padded row = x+1, col = y+1)
__device__ float4 g_pad[2][2][PD * PD];
__device__ float2 g_cs[NA];

__global__ void radon_prep(const float* __restrict__ x) {
    int i  = blockIdx.x * NTH + threadIdx.x;
    int lg = blockIdx.y;                    // 0..3: layout = lg>>1, group = lg&1
    if (lg == 0 && i < NA) {
        double t = (double)i * (M_PI / 360.0);   // 0.5 deg steps
        g_cs[i] = make_float2((float)cos(t), (float)sin(t));
    }
    if (i >= PD * PD) return;
    int layout = lg >> 1, g = lg & 1;
    int pr = i / PD, pc = i % PD;
    float4 v = make_float4(0.f, 0.f, 0.f, 0.f);
    if (pr >= 1 && pr <= D && pc >= 1 && pc <= D) {
        int yy = layout ? (pc - 1) : (pr - 1);
        int xx = layout ? (pr - 1) : (pc - 1);
        const float* p = x + ((size_t)g * 4) * (D * D) + yy * D + xx;
        v = make_float4(p[0], p[D * D], p[2 * D * D], p[3 * D * D]);
    }
    g_pad[layout][g][i] = v;
}

// Strip k covers padded rows [k*SR .. k*SR+9] = one contiguous block of 2580 float4.
__device__ __forceinline__ void strip_prefetch(const float4* __restrict__ src0,
                                               float4* buf, int tid) {
    const float4* s = src0 + tid;
    float4* d = buf + tid;
#pragma unroll
    for (int j = 0; j < 5; j++) {
        unsigned int da = (unsigned int)__cvta_generic_to_shared(d);
        asm volatile("cp.async.cg.shared.global [%0], [%1], 16;" :: "r"(da), "l"(s));
        s += NTH; d += NTH;
    }
    if (tid < STRIPF4 - 5 * NTH) {   // 2580 - 2560 = 20 leftovers
        unsigned int da = (unsigned int)__cvta_generic_to_shared(d);
        asm volatile("cp.async.cg.shared.global [%0], [%1], 16;" :: "r"(da), "l"(s));
    }
}

// CTA = (angle a, batch-group g). Thread (w ray, half); half splits each h-range.
// u = w-127.5, v = h-127.5:  ix = c*u - s*v + 127.5 ; iy = s*u + c*v + 127.5
// mode0 (|c|>=s): r=iy (rows), p=ix (cols), y-major layout.
// mode1 (s>|c|) : r=ix (rows), p=iy (cols), x-major layout.   |dr/dh| >= 0.707.
__global__ void __launch_bounds__(NTH, 2) radon_main(float* __restrict__ out) {
    extern __shared__ float4 sm[];
    const int a    = blockIdx.x;
    const int g    = blockIdx.y;
    const int tid  = threadIdx.x;
    const int w    = tid & (D - 1);
    const int half = tid >> 8;

    float2 cs = g_cs[a];
    float c = cs.x, s = cs.y;
    int   mode = (fabsf(c) >= s) ? 1 : 0;   // 1 => y-strip (layout 0)
    float r_u = mode ? s  : c;
    float r_v = mode ? c  : -s;
    float p_u = mode ? c  : s;
    float p_v = mode ? -s : c;
    const float4* __restrict__ base = g_pad[mode ? 0 : 1][g];

    float u    = (float)w - 127.5f;
    float A    = r_v;                                   // |A| >= 0.707
    float Bc   = fmaf(r_u, u, 127.5f * (1.0f - r_v));   // r(h) = A*h + Bc
    float Ap   = p_v;
    float Bp   = fmaf(p_u, u, 127.5f * (1.0f - p_v));   // p(h) = Ap*h + Bp
    float invA = 1.0f / A;
    float nBcInv = -Bc * invA;
    const float PMAXF = 255.99998f;                     // largest float < 256

    unsigned long long aXY = 0ull, aZW = 0ull;          // f32x2 accumulators

    strip_prefetch(base, sm, tid);
    asm volatile("cp.async.commit_group;");

    for (int k = 0; k < NS; k++) {
        if (k + 1 < NS) {
            strip_prefetch(base + (k + 1) * SR * PD, sm + ((k + 1) & 1) * STRIPF4, tid);
            asm volatile("cp.async.commit_group;");
            asm volatile("cp.async.wait_group 1;");
        } else {
            asm volatile("cp.async.wait_group 0;");
        }
        __syncthreads();
        const char* S = (const char*)(sm + (k & 1) * STRIPF4);

        const int lo    = k * SR;
        const int hi    = lo + SR - 1;
        const int loOwn = k ? lo : -1;          // strip 0 also owns floor(r) == -1
        const int span  = hi - loOwn;

        // widened h-range for floor(r) in [loOwn, hi]  <=>  r in [loOwn, hi+1)
        float e0 = fmaf((float)loOwn,    invA, nBcInv);
        float e1 = fmaf((float)(hi + 1), invA, nBcInv);
        float emin = fminf(e0, e1);
        float emax = fmaxf(e0, e1);
        int hbeg = max(0,     (int)floorf(emin) - 1);
        int hend = min(D - 1, (int)floorf(emax) + 1);
        int cnt  = hend - hbeg + 1; if (cnt < 0) cnt = 0;
        int ch   = (cnt + 1) >> 1;
        int ib   = half ? ch  : 0;
        int ie   = half ? cnt : ch;

        // corner byte address = Cb + sr*ROWB + sp*16, Cb = S + (1-lo)*ROWB + 16
        const char* Cb = S + (size_t)(1 - lo) * ROWB + 16;
        float fh = (float)(hbeg + ib);

        for (int i = ib; i < ie; i++) {
            float r = fmaf(A,  fh, Bc);
            float p = fmaf(Ap, fh, Bp);
            fh += 1.0f;
            p = fminf(fmaxf(p, -1.0f), PMAXF);
            int sr = __float2int_rd(r);
            int sp = __float2int_rd(p);
            if ((unsigned)(sr - loOwn) > (unsigned)span) continue;  // ownership
            float wr1 = r - (float)sr, wp1 = p - (float)sp;
            float wr0 = 1.0f - wr1,    wp0 = 1.0f - wp1;

            const char* A0 = Cb + sr * ROWB + sp * 16;
            ulonglong2 v00 = *(const ulonglong2*)(A0);
            ulonglong2 v01 = *(const ulonglong2*)(A0 + 16);
            ulonglong2 v10 = *(const ulonglong2*)(A0 + ROWB);
            ulonglong2 v11 = *(const ulonglong2*)(A0 + ROWB + 16);

            float w00 = wr0 * wp0, w01 = wr0 * wp1;
            float w10 = wr1 * wp0, w11 = wr1 * wp1;
            unsigned long long W;
            asm("mov.b64 %0,{%1,%1};" : "=l"(W) : "f"(w00));
            asm("fma.rn.f32x2 %0,%1,%2,%0;" : "+l"(aXY) : "l"(v00.x), "l"(W));
            asm("fma.rn.f32x2 %0,%1,%2,%0;" : "+l"(aZW) : "l"(v00.y), "l"(W));
            asm("mov.b64 %0,{%1,%1};" : "=l"(W) : "f"(w01));
            asm("fma.rn.f32x2 %0,%1,%2,%0;" : "+l"(aXY) : "l"(v01.x), "l"(W));
            asm("fma.rn.f32x2 %0,%1,%2,%0;" : "+l"(aZW) : "l"(v01.y), "l"(W));
            asm("mov.b64 %0,{%1,%1};" : "=l"(W) : "f"(w10));
            asm("fma.rn.f32x2 %0,%1,%2,%0;" : "+l"(aXY) : "l"(v10.x), "l"(W));
            asm("fma.rn.f32x2 %0,%1,%2,%0;" : "+l"(aZW) : "l"(v10.y), "l"(W));
            asm("mov.b64 %0,{%1,%1};" : "=l"(W) : "f"(w11));
            asm("fma.rn.f32x2 %0,%1,%2,%0;" : "+l"(aXY) : "l"(v11.x), "l"(W));
            asm("fma.rn.f32x2 %0,%1,%2,%0;" : "+l"(aZW) : "l"(v11.y), "l"(W));
        }
        __syncthreads();
    }

    float ax, ay, az, aw;
    asm("mov.b64 {%0,%1},%2;" : "=f"(ax), "=f"(ay) : "l"(aXY));
    asm("mov.b64 {%0,%1},%2;" : "=f"(az), "=f"(aw) : "l"(aZW));

    // reduce halves via smem (last loop iteration ended with __syncthreads)
    if (half == 1) sm[w] = make_float4(ax, ay, az, aw);
    __syncthreads();
    if (half == 0) {
        float4 o = sm[w];
        ax += o.x; ay += o.y; az += o.z; aw += o.w;
        const float sc = 1.0f / 256.0f;
        int b0 = g * 4;
        out[((b0 + 0) * NA + a) * D + w] = ax * sc;
        out[((b0 + 1) * NA + a) * D + w] = ay * sc;
        out[((b0 + 2) * NA + a) * D + w] = az * sc;
        out[((b0 + 3) * NA + a) * D + w] = aw * sc;
    }
}

extern "C" void kernel_launch(void* const* d_in, const int* in_sizes, int n_in,
                              void* d_out, int out_size) {
    const float* x = (const float*)d_in[0];
    float* out = (float*)d_out;
    cudaFuncSetAttribute(radon_main, cudaFuncAttributeMaxDynamicSharedMemorySize, SMEMB);
    radon_prep<<<dim3((PD * PD + NTH - 1) / NTH, 4), NTH>>>(x);
    radon_main<<<dim3(NA, 2), NTH, SMEMB>>>(out);
}